// round 6
// baseline (speedup 1.0000x reference)
#include <cuda_runtime.h>
#include <cuda_bf16.h>

// Problem constants
#define BB   64
#define DPT  128
#define HW   121     // 11*11
#define OCH  16

typedef unsigned long long u64;

union F2U { u64 u; float2 f; };

__device__ __forceinline__ u64 fma2(u64 a, u64 b, u64 c) {
    u64 d;
    asm("fma.rn.f32x2 %0, %1, %2, %3;" : "=l"(d) : "l"(a), "l"(b), "l"(c));
    return d;
}
__device__ __forceinline__ u64 dup2(float w) {
    u64 d;
    asm("mov.b64 %0, {%1, %1};" : "=l"(d) : "f"(w));
    return d;
}

// Scratch (device globals: allocation-free)
__device__ float g_sa1[BB*OCH*DPT*HW];
__device__ float g_sa2[BB*OCH*DPT*HW];
__device__ float g_sa3[BB*OCH*DPT*HW];
__device__ float g_feat[5*BB*OCH*HW];   // 5 feats of (B,16,11,11)
__device__ float g_wT[3*16128];         // transposed weights per layer

// Weights for the active conv layer, transposed [(i*63 + kd*9 + khw)*16 + o]
__constant__ float c_w[16128];          // 64512 B <= 64KB constant bank

#define FEAT_SZ (OCH*HW)         // 1936

// ---------------------------------------------------------------------------
// transpose weights: dst[(i*63+r)*16 + o] = wt[o*(ich*63) + i*63 + r]
// ---------------------------------------------------------------------------
__global__ void transpose_w_kernel(const float* __restrict__ wt, float* __restrict__ dst, int ich)
{
    int t = blockIdx.x*blockDim.x + threadIdx.x;
    int n = OCH*ich*63;
    if (t < n) {
        int o = t / (ich*63);
        int r = t - o*(ich*63);
        dst[r*16 + o] = wt[t];
    }
}

// ---------------------------------------------------------------------------
// 3D conv, packed f32x2 FMAs over DEPTH PAIRS, weights in __constant__,
// register-cached depth column per spatial tap.
//
// Loop order: ii (in-channel) -> khw (spatial tap, unroll 1) -> kd (unrolled 7).
// For one tap, the 13 depth rows at that spatial offset are loaded ONCE into
// registers (13 x LDS.64), then consumed by all (kd, depth-pair) combos:
// row t[kd + 2r] feeds depth-pair r at kernel depth kd. Input smem traffic
// drops 252 -> 117 LDS.64 per ii per thread; weights ride the constant port
// (LDC.128) which is off the l1tex return path.
// ---------------------------------------------------------------------------
template<int ICH, int CHK>
__global__ void __launch_bounds__(256, 2) conv3d6_kernel(
    const float* __restrict__ in,
    const float* __restrict__ bias, float* __restrict__ out)
{
    const int d0 = blockIdx.x * 8;
    const int b  = blockIdx.y;
    extern __shared__ float2 in2[];                 // CHK*13*169 float2 (depth pairs)
    const int tid = threadIdx.x;

    const int og  = tid >> 7;
    const int pos = tid & 127;
    const int cpos = pos < HW ? pos : HW-1;       // clamp dead lanes (no smem OOB)
    const int h = cpos / 11, w = cpos - h*11;
    const int ppc = (h+1)*13 + (w+1);

    u64 acc[4][8];   // [depth-pair][out-channel]
    #pragma unroll
    for (int r = 0; r < 4; r++)
        #pragma unroll
        for (int o = 0; o < 8; o++) acc[r][o] = 0ULL;

    for (int c0 = 0; c0 < ICH; c0 += CHK) {
        __syncthreads();
        // stage input depth-pairs: rows dd=0..12, value (in[gd], in[gd+1]), gd=d0-3+dd
        for (int t = tid; t < CHK*13*169; t += 256) {
            int ii  = t / (13*169);
            int rem = t - ii*(13*169);
            int dd  = rem / 169;
            int pp  = rem - dd*169;
            int h13 = pp / 13, w13 = pp - h13*13;
            int gd  = d0 - 3 + dd;
            float v0 = 0.f, v1 = 0.f;
            if (h13 >= 1 && h13 <= 11 && w13 >= 1 && w13 <= 11) {
                const float* src = in + ((size_t)(b*ICH + c0 + ii)*DPT)*HW + (h13-1)*11 + (w13-1);
                if (gd   >= 0 && gd   < DPT) v0 = src[(size_t)gd*HW];
                if (gd+1 >= 0 && gd+1 < DPT) v1 = src[(size_t)(gd+1)*HW];
            }
            in2[t] = make_float2(v0, v1);
        }
        __syncthreads();

        for (int ii = 0; ii < CHK; ++ii) {
            const u64* col   = (const u64*)in2 + (ii*13)*169 + ppc;
            const int  wbase = (c0 + ii)*63*16 + og*8;
            #pragma unroll 1
            for (int khw = 0; khw < 9; ++khw) {
                const int kh = khw / 3, kw = khw - kh*3;
                const int off = (kh - 1)*13 + (kw - 1);
                // register-cache the 13 depth rows at this spatial tap
                u64 t[13];
                #pragma unroll
                for (int j = 0; j < 13; ++j) t[j] = col[j*169 + off];
                #pragma unroll
                for (int kd = 0; kd < 7; ++kd) {
                    // weights from constant bank (LDC.128) — off the l1tex path
                    const int wk = wbase + (kd*9 + khw)*16;
                    float4 wa = *reinterpret_cast<const float4*>(&c_w[wk]);
                    float4 wc = *reinterpret_cast<const float4*>(&c_w[wk + 4]);
                    u64 wd[8];
                    wd[0] = dup2(wa.x); wd[1] = dup2(wa.y);
                    wd[2] = dup2(wa.z); wd[3] = dup2(wa.w);
                    wd[4] = dup2(wc.x); wd[5] = dup2(wc.y);
                    wd[6] = dup2(wc.z); wd[7] = dup2(wc.w);
                    #pragma unroll
                    for (int r = 0; r < 4; ++r) {
                        u64 a = t[kd + 2*r];
                        #pragma unroll
                        for (int o = 0; o < 8; ++o)
                            acc[r][o] = fma2(a, wd[o], acc[r][o]);
                    }
                }
            }
        }
    }

    if (pos < HW) {
        #pragma unroll
        for (int o = 0; o < 8; ++o) {
            const int oc = og*8 + o;
            const float bv = bias[oc];
            float* ob = out + ((size_t)(b*OCH + oc)*DPT + d0)*HW + pos;
            #pragma unroll
            for (int r = 0; r < 4; ++r) {
                F2U a; a.u = acc[r][o];
                float v0 = a.f.x + bv;
                float v1 = a.f.y + bv;
                ob[(2*r  )*HW] = v0 > 0.f ? v0 : 0.f;
                ob[(2*r+1)*HW] = v1 > 0.f ? v1 : 0.f;
            }
        }
    }
}

// ---------------------------------------------------------------------------
// cpr: feat[b,o,p] = relu( sum_d sa[b,o,d,p] * softmax(cw[o,:])[d] )
// ---------------------------------------------------------------------------
__global__ void cpr_kernel(const float* __restrict__ sa, const float* __restrict__ cw,
                           float* __restrict__ feat)
{
    const int o = blockIdx.x, b = blockIdx.y, tid = threadIdx.x;
    __shared__ float a_s[128];
    __shared__ float red[128];
    float wv = cw[o*128 + tid];
    red[tid] = wv; __syncthreads();
    for (int s = 64; s > 0; s >>= 1) { if (tid < s) red[tid] = fmaxf(red[tid], red[tid+s]); __syncthreads(); }
    float mx = red[0]; __syncthreads();
    float e = expf(wv - mx);
    red[tid] = e; __syncthreads();
    for (int s = 64; s > 0; s >>= 1) { if (tid < s) red[tid] += red[tid+s]; __syncthreads(); }
    a_s[tid] = e / red[0];
    __syncthreads();
    if (tid < HW) {
        const float* base = sa + ((size_t)(b*16 + o)*DPT)*HW + tid;
        float acc = 0.f;
        #pragma unroll 4
        for (int d = 0; d < 128; ++d) acc += base[d*HW] * a_s[d];
        feat[(b*16 + o)*HW + tid] = acc > 0.f ? acc : 0.f;
    }
}

// ---------------------------------------------------------------------------
// conv4/conv5 2D: relu(conv2d(3x3,pad1)) twice. One block per batch.
// ---------------------------------------------------------------------------
__global__ void conv45_kernel(const float* __restrict__ feat2,
                              const float* __restrict__ w45, const float* __restrict__ b45,
                              float* __restrict__ feat3, float* __restrict__ feat4)
{
    const int b = blockIdx.x, tid = threadIdx.x;
    __shared__ float fa[FEAT_SZ], fb[FEAT_SZ];
    for (int t = tid; t < FEAT_SZ; t += 128) fa[t] = feat2[b*FEAT_SZ + t];
    __syncthreads();
    if (tid < HW) {
        int h = tid / 11, w = tid - h*11;
        for (int o = 0; o < 16; o++) {
            float acc = b45[o];
            for (int c = 0; c < 16; c++)
                #pragma unroll
                for (int kh = 0; kh < 3; kh++) {
                    int hh = h + kh - 1; if (hh < 0 || hh >= 11) continue;
                    #pragma unroll
                    for (int kw = 0; kw < 3; kw++) {
                        int ww2 = w + kw - 1; if (ww2 < 0 || ww2 >= 11) continue;
                        acc += fa[c*HW + hh*11 + ww2] * w45[(o*16 + c)*9 + kh*3 + kw];
                    }
                }
            float v = acc > 0.f ? acc : 0.f;
            fb[o*HW + tid] = v;
            feat3[b*FEAT_SZ + o*HW + tid] = v;
        }
    }
    __syncthreads();
    if (tid < HW) {
        int h = tid / 11, w = tid - h*11;
        for (int o = 0; o < 16; o++) {
            float acc = b45[16 + o];
            for (int c = 0; c < 16; c++)
                #pragma unroll
                for (int kh = 0; kh < 3; kh++) {
                    int hh = h + kh - 1; if (hh < 0 || hh >= 11) continue;
                    #pragma unroll
                    for (int kw = 0; kw < 3; kw++) {
                        int ww2 = w + kw - 1; if (ww2 < 0 || ww2 >= 11) continue;
                        acc += fb[c*HW + hh*11 + ww2] * w45[2304 + (o*16 + c)*9 + kh*3 + kw];
                    }
                }
            float v = acc > 0.f ? acc : 0.f;
            feat4[b*FEAT_SZ + o*HW + tid] = v;
        }
    }
}

// ---------------------------------------------------------------------------
// Side head: per (side i, batch b). Sideout, seg conv, top-5 similar sum,
// receptive-field-reduced sp branch (only 7x7 ratio patch matters), fuse.
// ---------------------------------------------------------------------------
__global__ void side_kernel(const float* __restrict__ x, const float* __restrict__ feat,
    const float* __restrict__ sw,  const float* __restrict__ sb,
    const float* __restrict__ sow, const float* __restrict__ sob,
    const float* __restrict__ wa,  const float* __restrict__ ba,
    const float* __restrict__ wb,  const float* __restrict__ bbv,
    const float* __restrict__ ssw, const float* __restrict__ ssb,
    const float* __restrict__ fuse, float* __restrict__ out)
{
    const int i = blockIdx.x, b = blockIdx.y, tid = threadIdx.x;
    __shared__ float f_s[FEAT_SZ], act_s[HW], diff_s[HW], s_arr[128], xc[128], y1_s[144], y2_s[16];
    __shared__ int idx_s[5];

    for (int t = tid; t < FEAT_SZ; t += 128)
        f_s[t] = feat[i*(BB*FEAT_SZ) + b*FEAT_SZ + t];
    __syncthreads();

    // seg conv (no relu)
    if (tid < HW) {
        int h = tid / 11, w = tid - h*11;
        float acc = sb[i];
        for (int c = 0; c < 16; c++)
            #pragma unroll
            for (int kh = 0; kh < 3; kh++) {
                int hh = h + kh - 1; if (hh < 0 || hh >= 11) continue;
                #pragma unroll
                for (int kw = 0; kw < 3; kw++) {
                    int ww2 = w + kw - 1; if (ww2 < 0 || ww2 >= 11) continue;
                    acc += f_s[c*HW + hh*11 + ww2] * sw[(i*16 + c)*9 + kh*3 + kw];
                }
            }
        act_s[tid] = acc;
    }
    __syncthreads();
    if (tid < HW) diff_s[tid] = fabsf(act_s[tid] - act_s[60]);
    __syncthreads();
    // top-5 smallest diff, stable (lowest index on ties) — matches jax top_k(-diff)
    if (tid == 0) {
        for (int j = 0; j < 5; j++) {
            float best = 3.4e38f; int bi = 0;
            for (int p = 0; p < HW; p++) { float d = diff_s[p]; if (d < best) { best = d; bi = p; } }
            idx_s[j] = bi; diff_s[bi] = 3.4e38f;
        }
    }
    __syncthreads();
    // similar-sum s[c] and center xc[c]
    {
        float s = 0.f;
        const float* xb = x + (size_t)(b*128 + tid)*HW;
        #pragma unroll
        for (int j = 0; j < 5; j++) s += xb[idx_s[j]];
        s_arr[tid] = s;
        xc[tid] = xb[60];
    }
    __syncthreads();
    // y1 at the 9 positions {62,64,66}^2 feeding the dil-2 conv center
    for (int t = tid; t < 144; t += 128) {
        int o = t / 9, j = t - o*9;
        int pj = 62 + 2*(j/3), qj = 62 + 2*(j%3);
        float acc = ba[i*16 + o];
        #pragma unroll
        for (int ch = 0; ch < 2; ch++) {
            const float* num = ch ? xc : s_arr;
            #pragma unroll
            for (int eh = 0; eh < 3; eh++)
                #pragma unroll
                for (int ew = 0; ew < 3; ew++) {
                    int r = pj + eh - 1, c = qj + ew - 1;
                    float den = num[c];
                    den = fabsf(den) < 0.01f ? 0.01f : den;
                    float img = num[r] / den;
                    acc += img * wa[(((i*16 + o)*2 + ch)*3 + eh)*3 + ew];
                }
        }
        y1_s[o*9 + j] = acc > 0.f ? acc : 0.f;
    }
    __syncthreads();
    // y2 center (dil-2 conv), relu
    if (tid < 16) {
        float acc = bbv[i*16 + tid];
        for (int c = 0; c < 16; c++)
            #pragma unroll
            for (int j = 0; j < 9; j++)
                acc += y1_s[c*9 + j] * wb[((i*16 + tid)*16 + c)*9 + j];
        y2_s[tid] = acc > 0.f ? acc : 0.f;
    }
    __syncthreads();
    // sideouts + fuse
    if (tid < 16) {
        float sa_v = sob[i*16 + tid];
        for (int k = 0; k < 16; k++) sa_v += f_s[k*HW + 60] * sow[(i*16 + tid)*16 + k];
        float sp_v = ssb[i*16 + tid];
        for (int c = 0; c < 16; c++) sp_v += y2_s[c] * ssw[(i*16 + tid)*16 + c];
        atomicAdd(&out[b*16 + tid], fuse[i]*sa_v + fuse[5 + i]*sp_v);
    }
}

__global__ void zero_kernel(float* out, int n)
{
    int t = blockIdx.x*blockDim.x + threadIdx.x;
    if (t < n) out[t] = 0.f;
}

// ---------------------------------------------------------------------------
extern "C" void kernel_launch(void* const* d_in, const int* in_sizes, int n_in,
                              void* d_out, int out_size)
{
    const float* x      = (const float*)d_in[0];
    const float* w3d1   = (const float*)d_in[1];
    const float* b3d1   = (const float*)d_in[2];
    const float* w3d23  = (const float*)d_in[3];
    const float* b3d23  = (const float*)d_in[4];
    const float* cpr_w  = (const float*)d_in[5];
    const float* w2d45  = (const float*)d_in[6];
    const float* b2d45  = (const float*)d_in[7];
    const float* seg_w  = (const float*)d_in[8];
    const float* seg_b  = (const float*)d_in[9];
    const float* so_w   = (const float*)d_in[10];
    const float* so_b   = (const float*)d_in[11];
    const float* sp_wa  = (const float*)d_in[12];
    const float* sp_ba  = (const float*)d_in[13];
    const float* sp_wb  = (const float*)d_in[14];
    const float* sp_bb  = (const float*)d_in[15];
    const float* sp_sw  = (const float*)d_in[16];
    const float* sp_sb  = (const float*)d_in[17];
    const float* fuse   = (const float*)d_in[18];
    float* out = (float*)d_out;

    float *sa1, *sa2, *sa3, *feat, *wT;
    cudaGetSymbolAddress((void**)&sa1,  g_sa1);
    cudaGetSymbolAddress((void**)&sa2,  g_sa2);
    cudaGetSymbolAddress((void**)&sa3,  g_sa3);
    cudaGetSymbolAddress((void**)&feat, g_feat);
    cudaGetSymbolAddress((void**)&wT,   g_wT);

    const int SMEM16 = 4*13*169*8;   // 70,304 B (input pairs only; 2 blocks/SM)
    const int SMEM1  = 1*13*169*8;   // 17,576 B
    cudaFuncSetAttribute((const void*)conv3d6_kernel<16,4>, cudaFuncAttributeMaxDynamicSharedMemorySize, SMEM16);
    cudaFuncSetAttribute((const void*)conv3d6_kernel<1,1>,  cudaFuncAttributeMaxDynamicSharedMemorySize, SMEM1);

    // transpose all layer weights up-front
    transpose_w_kernel<<<(1008 + 255)/256, 256>>>(w3d1,           wT + 0*16128, 1);
    transpose_w_kernel<<<(16128 + 255)/256, 256>>>(w3d23,         wT + 1*16128, 16);
    transpose_w_kernel<<<(16128 + 255)/256, 256>>>(w3d23 + 16128, wT + 2*16128, 16);

    zero_kernel<<<(out_size + 255)/256, 256>>>(out, out_size);

    cudaMemcpyToSymbolAsync(c_w, wT + 0*16128, 1008*4, 0, cudaMemcpyDeviceToDevice, 0);
    conv3d6_kernel<1,1><<<dim3(16, BB), 256, SMEM1>>>(x, b3d1, sa1);
    cpr_kernel<<<dim3(16, BB), 128>>>(sa1, cpr_w + 0*2048, feat + 0*(BB*FEAT_SZ));

    cudaMemcpyToSymbolAsync(c_w, wT + 1*16128, 16128*4, 0, cudaMemcpyDeviceToDevice, 0);
    conv3d6_kernel<16,4><<<dim3(16, BB), 256, SMEM16>>>(sa1, b3d23, sa2);
    cpr_kernel<<<dim3(16, BB), 128>>>(sa2, cpr_w + 1*2048, feat + 1*(BB*FEAT_SZ));

    cudaMemcpyToSymbolAsync(c_w, wT + 2*16128, 16128*4, 0, cudaMemcpyDeviceToDevice, 0);
    conv3d6_kernel<16,4><<<dim3(16, BB), 256, SMEM16>>>(sa2, b3d23 + 16, sa3);
    cpr_kernel<<<dim3(16, BB), 128>>>(sa3, cpr_w + 2*2048, feat + 2*(BB*FEAT_SZ));

    conv45_kernel<<<BB, 128>>>(feat + 2*(BB*FEAT_SZ), w2d45, b2d45,
                               feat + 3*(BB*FEAT_SZ), feat + 4*(BB*FEAT_SZ));

    side_kernel<<<dim3(5, BB), 128>>>(x, feat, seg_w, seg_b, so_w, so_b,
                                      sp_wa, sp_ba, sp_wb, sp_bb, sp_sw, sp_sb,
                                      fuse, out);
}

// round 7
// speedup vs baseline: 1.0201x; 1.0201x over previous
#include <cuda_runtime.h>
#include <cuda_bf16.h>

// Problem constants
#define BB   64
#define DPT  128
#define HW   121     // 11*11
#define OCH  16

typedef unsigned long long u64;

union F2U { u64 u; float2 f; };

__device__ __forceinline__ u64 fma2(u64 a, u64 b, u64 c) {
    u64 d;
    asm("fma.rn.f32x2 %0, %1, %2, %3;" : "=l"(d) : "l"(a), "l"(b), "l"(c));
    return d;
}
__device__ __forceinline__ u64 dup2(float w) {
    u64 d;
    asm("mov.b64 %0, {%1, %1};" : "=l"(d) : "f"(w));
    return d;
}

// Scratch (device globals: allocation-free)
__device__ float g_sa1[BB*OCH*DPT*HW];
__device__ float g_sa2[BB*OCH*DPT*HW];
__device__ float g_sa3[BB*OCH*DPT*HW];
__device__ float g_feat[5*BB*OCH*HW];   // 5 feats of (B,16,11,11)

#define FEAT_SZ (OCH*HW)         // 1936

// ---------------------------------------------------------------------------
// 3D conv, packed f32x2 FMAs over DEPTH PAIRS, smem weights (uniform LDS.128),
// register-cached depth column per spatial tap.
//
// Loop order: ii (in-channel) -> khw (spatial tap, unroll 1) -> kd (unrolled 7).
// For one tap, the 13 depth rows at that spatial offset are loaded ONCE into
// registers (13 x LDS.64) and consumed by all (kd, depth-pair) combos:
// row t[kd + 2r] feeds depth-pair r at kernel depth kd.
// Per khw per warp: 13 LDS.64 input (3328B) + 14 LDS.128 weights (7168B)
// vs 224 FFMA2/thread -> fma is the limiter (L1/FMA ~= 0.73).
// ---------------------------------------------------------------------------
template<int ICH, int CHK>
__global__ void __launch_bounds__(256, 2) conv3d7_kernel(
    const float* __restrict__ in, const float* __restrict__ wt,
    const float* __restrict__ bias, float* __restrict__ out)
{
    const int d0 = blockIdx.x * 8;
    const int b  = blockIdx.y;
    extern __shared__ float sm[];
    float*  w_s = sm;                               // CHK*63*16 floats
    float2* in2 = (float2*)(sm + CHK*63*16);        // CHK*13*169 float2 (depth pairs)
    const int tid = threadIdx.x;

    const int og  = tid >> 7;
    const int pos = tid & 127;
    const int cpos = pos < HW ? pos : HW-1;       // clamp dead lanes (no smem OOB)
    const int h = cpos / 11, w = cpos - h*11;
    const int ppc = (h+1)*13 + (w+1);

    u64 acc[4][8];   // [depth-pair][out-channel]
    #pragma unroll
    for (int r = 0; r < 4; r++)
        #pragma unroll
        for (int o = 0; o < 8; o++) acc[r][o] = 0ULL;

    for (int c0 = 0; c0 < ICH; c0 += CHK) {
        __syncthreads();
        // stage weights: src wt[o][(c0+ii)*63 + r] -> w_s[(ii*63+r)*16 + o]
        for (int t = tid; t < OCH*CHK*63; t += 256) {
            int o = t / (CHK*63);
            int r = t - o*(CHK*63);
            w_s[r*16 + o] = wt[o*(ICH*63) + c0*63 + r];
        }
        // stage input depth-pairs: rows dd=0..12, value (in[gd], in[gd+1]), gd=d0-3+dd
        for (int t = tid; t < CHK*13*169; t += 256) {
            int ii  = t / (13*169);
            int rem = t - ii*(13*169);
            int dd  = rem / 169;
            int pp  = rem - dd*169;
            int h13 = pp / 13, w13 = pp - h13*13;
            int gd  = d0 - 3 + dd;
            float v0 = 0.f, v1 = 0.f;
            if (h13 >= 1 && h13 <= 11 && w13 >= 1 && w13 <= 11) {
                const float* src = in + ((size_t)(b*ICH + c0 + ii)*DPT)*HW + (h13-1)*11 + (w13-1);
                if (gd   >= 0 && gd   < DPT) v0 = src[(size_t)gd*HW];
                if (gd+1 >= 0 && gd+1 < DPT) v1 = src[(size_t)(gd+1)*HW];
            }
            in2[t] = make_float2(v0, v1);
        }
        __syncthreads();

        for (int ii = 0; ii < CHK; ++ii) {
            const u64*   col = (const u64*)in2 + (ii*13)*169 + ppc;
            const float* wb  = w_s + ii*63*16 + og*8;
            #pragma unroll 1
            for (int khw = 0; khw < 9; ++khw) {
                const int kh = khw / 3, kw = khw - kh*3;
                const int off = (kh - 1)*13 + (kw - 1);
                // register-cache the 13 depth rows at this spatial tap
                u64 t[13];
                #pragma unroll
                for (int j = 0; j < 13; ++j) t[j] = col[j*169 + off];
                #pragma unroll
                for (int kd = 0; kd < 7; ++kd) {
                    // uniform (per-warp) weight loads from smem
                    const float* wk = wb + (kd*9 + khw)*16;
                    float4 wa = *reinterpret_cast<const float4*>(wk);
                    float4 wc = *reinterpret_cast<const float4*>(wk + 4);
                    u64 wd[8];
                    wd[0] = dup2(wa.x); wd[1] = dup2(wa.y);
                    wd[2] = dup2(wa.z); wd[3] = dup2(wa.w);
                    wd[4] = dup2(wc.x); wd[5] = dup2(wc.y);
                    wd[6] = dup2(wc.z); wd[7] = dup2(wc.w);
                    #pragma unroll
                    for (int r = 0; r < 4; ++r) {
                        u64 a = t[kd + 2*r];
                        #pragma unroll
                        for (int o = 0; o < 8; ++o)
                            acc[r][o] = fma2(a, wd[o], acc[r][o]);
                    }
                }
            }
        }
    }

    if (pos < HW) {
        #pragma unroll
        for (int o = 0; o < 8; ++o) {
            const int oc = og*8 + o;
            const float bv = bias[oc];
            float* ob = out + ((size_t)(b*OCH + oc)*DPT + d0)*HW + pos;
            #pragma unroll
            for (int r = 0; r < 4; ++r) {
                F2U a; a.u = acc[r][o];
                float v0 = a.f.x + bv;
                float v1 = a.f.y + bv;
                ob[(2*r  )*HW] = v0 > 0.f ? v0 : 0.f;
                ob[(2*r+1)*HW] = v1 > 0.f ? v1 : 0.f;
            }
        }
    }
}

// ---------------------------------------------------------------------------
// cpr: feat[b,o,p] = relu( sum_d sa[b,o,d,p] * softmax(cw[o,:])[d] )
// ---------------------------------------------------------------------------
__global__ void cpr_kernel(const float* __restrict__ sa, const float* __restrict__ cw,
                           float* __restrict__ feat)
{
    const int o = blockIdx.x, b = blockIdx.y, tid = threadIdx.x;
    __shared__ float a_s[128];
    __shared__ float red[128];
    float wv = cw[o*128 + tid];
    red[tid] = wv; __syncthreads();
    for (int s = 64; s > 0; s >>= 1) { if (tid < s) red[tid] = fmaxf(red[tid], red[tid+s]); __syncthreads(); }
    float mx = red[0]; __syncthreads();
    float e = expf(wv - mx);
    red[tid] = e; __syncthreads();
    for (int s = 64; s > 0; s >>= 1) { if (tid < s) red[tid] += red[tid+s]; __syncthreads(); }
    a_s[tid] = e / red[0];
    __syncthreads();
    if (tid < HW) {
        const float* base = sa + ((size_t)(b*16 + o)*DPT)*HW + tid;
        float acc = 0.f;
        #pragma unroll 4
        for (int d = 0; d < 128; ++d) acc += base[d*HW] * a_s[d];
        feat[(b*16 + o)*HW + tid] = acc > 0.f ? acc : 0.f;
    }
}

// ---------------------------------------------------------------------------
// conv4/conv5 2D: relu(conv2d(3x3,pad1)) twice. One block per batch.
// ---------------------------------------------------------------------------
__global__ void conv45_kernel(const float* __restrict__ feat2,
                              const float* __restrict__ w45, const float* __restrict__ b45,
                              float* __restrict__ feat3, float* __restrict__ feat4)
{
    const int b = blockIdx.x, tid = threadIdx.x;
    __shared__ float fa[FEAT_SZ], fb[FEAT_SZ];
    for (int t = tid; t < FEAT_SZ; t += 128) fa[t] = feat2[b*FEAT_SZ + t];
    __syncthreads();
    if (tid < HW) {
        int h = tid / 11, w = tid - h*11;
        for (int o = 0; o < 16; o++) {
            float acc = b45[o];
            for (int c = 0; c < 16; c++)
                #pragma unroll
                for (int kh = 0; kh < 3; kh++) {
                    int hh = h + kh - 1; if (hh < 0 || hh >= 11) continue;
                    #pragma unroll
                    for (int kw = 0; kw < 3; kw++) {
                        int ww2 = w + kw - 1; if (ww2 < 0 || ww2 >= 11) continue;
                        acc += fa[c*HW + hh*11 + ww2] * w45[(o*16 + c)*9 + kh*3 + kw];
                    }
                }
            float v = acc > 0.f ? acc : 0.f;
            fb[o*HW + tid] = v;
            feat3[b*FEAT_SZ + o*HW + tid] = v;
        }
    }
    __syncthreads();
    if (tid < HW) {
        int h = tid / 11, w = tid - h*11;
        for (int o = 0; o < 16; o++) {
            float acc = b45[16 + o];
            for (int c = 0; c < 16; c++)
                #pragma unroll
                for (int kh = 0; kh < 3; kh++) {
                    int hh = h + kh - 1; if (hh < 0 || hh >= 11) continue;
                    #pragma unroll
                    for (int kw = 0; kw < 3; kw++) {
                        int ww2 = w + kw - 1; if (ww2 < 0 || ww2 >= 11) continue;
                        acc += fb[c*HW + hh*11 + ww2] * w45[2304 + (o*16 + c)*9 + kh*3 + kw];
                    }
                }
            float v = acc > 0.f ? acc : 0.f;
            feat4[b*FEAT_SZ + o*HW + tid] = v;
        }
    }
}

// ---------------------------------------------------------------------------
// Side head: per (side i, batch b). Sideout, seg conv, top-5 similar sum,
// receptive-field-reduced sp branch (only 7x7 ratio patch matters), fuse.
// ---------------------------------------------------------------------------
__global__ void side_kernel(const float* __restrict__ x, const float* __restrict__ feat,
    const float* __restrict__ sw,  const float* __restrict__ sb,
    const float* __restrict__ sow, const float* __restrict__ sob,
    const float* __restrict__ wa,  const float* __restrict__ ba,
    const float* __restrict__ wb,  const float* __restrict__ bbv,
    const float* __restrict__ ssw, const float* __restrict__ ssb,
    const float* __restrict__ fuse, float* __restrict__ out)
{
    const int i = blockIdx.x, b = blockIdx.y, tid = threadIdx.x;
    __shared__ float f_s[FEAT_SZ], act_s[HW], diff_s[HW], s_arr[128], xc[128], y1_s[144], y2_s[16];
    __shared__ int idx_s[5];

    for (int t = tid; t < FEAT_SZ; t += 128)
        f_s[t] = feat[i*(BB*FEAT_SZ) + b*FEAT_SZ + t];
    __syncthreads();

    // seg conv (no relu)
    if (tid < HW) {
        int h = tid / 11, w = tid - h*11;
        float acc = sb[i];
        for (int c = 0; c < 16; c++)
            #pragma unroll
            for (int kh = 0; kh < 3; kh++) {
                int hh = h + kh - 1; if (hh < 0 || hh >= 11) continue;
                #pragma unroll
                for (int kw = 0; kw < 3; kw++) {
                    int ww2 = w + kw - 1; if (ww2 < 0 || ww2 >= 11) continue;
                    acc += f_s[c*HW + hh*11 + ww2] * sw[(i*16 + c)*9 + kh*3 + kw];
                }
            }
        act_s[tid] = acc;
    }
    __syncthreads();
    if (tid < HW) diff_s[tid] = fabsf(act_s[tid] - act_s[60]);
    __syncthreads();
    // top-5 smallest diff, stable (lowest index on ties) — matches jax top_k(-diff)
    if (tid == 0) {
        for (int j = 0; j < 5; j++) {
            float best = 3.4e38f; int bi = 0;
            for (int p = 0; p < HW; p++) { float d = diff_s[p]; if (d < best) { best = d; bi = p; } }
            idx_s[j] = bi; diff_s[bi] = 3.4e38f;
        }
    }
    __syncthreads();
    // similar-sum s[c] and center xc[c]
    {
        float s = 0.f;
        const float* xb = x + (size_t)(b*128 + tid)*HW;
        #pragma unroll
        for (int j = 0; j < 5; j++) s += xb[idx_s[j]];
        s_arr[tid] = s;
        xc[tid] = xb[60];
    }
    __syncthreads();
    // y1 at the 9 positions {62,64,66}^2 feeding the dil-2 conv center
    for (int t = tid; t < 144; t += 128) {
        int o = t / 9, j = t - o*9;
        int pj = 62 + 2*(j/3), qj = 62 + 2*(j%3);
        float acc = ba[i*16 + o];
        #pragma unroll
        for (int ch = 0; ch < 2; ch++) {
            const float* num = ch ? xc : s_arr;
            #pragma unroll
            for (int eh = 0; eh < 3; eh++)
                #pragma unroll
                for (int ew = 0; ew < 3; ew++) {
                    int r = pj + eh - 1, c = qj + ew - 1;
                    float den = num[c];
                    den = fabsf(den) < 0.01f ? 0.01f : den;
                    float img = num[r] / den;
                    acc += img * wa[(((i*16 + o)*2 + ch)*3 + eh)*3 + ew];
                }
        }
        y1_s[o*9 + j] = acc > 0.f ? acc : 0.f;
    }
    __syncthreads();
    // y2 center (dil-2 conv), relu
    if (tid < 16) {
        float acc = bbv[i*16 + tid];
        for (int c = 0; c < 16; c++)
            #pragma unroll
            for (int j = 0; j < 9; j++)
                acc += y1_s[c*9 + j] * wb[((i*16 + tid)*16 + c)*9 + j];
        y2_s[tid] = acc > 0.f ? acc : 0.f;
    }
    __syncthreads();
    // sideouts + fuse
    if (tid < 16) {
        float sa_v = sob[i*16 + tid];
        for (int k = 0; k < 16; k++) sa_v += f_s[k*HW + 60] * sow[(i*16 + tid)*16 + k];
        float sp_v = ssb[i*16 + tid];
        for (int c = 0; c < 16; c++) sp_v += y2_s[c] * ssw[(i*16 + tid)*16 + c];
        atomicAdd(&out[b*16 + tid], fuse[i]*sa_v + fuse[5 + i]*sp_v);
    }
}

__global__ void zero_kernel(float* out, int n)
{
    int t = blockIdx.x*blockDim.x + threadIdx.x;
    if (t < n) out[t] = 0.f;
}

// ---------------------------------------------------------------------------
extern "C" void kernel_launch(void* const* d_in, const int* in_sizes, int n_in,
                              void* d_out, int out_size)
{
    const float* x      = (const float*)d_in[0];
    const float* w3d1   = (const float*)d_in[1];
    const float* b3d1   = (const float*)d_in[2];
    const float* w3d23  = (const float*)d_in[3];
    const float* b3d23  = (const float*)d_in[4];
    const float* cpr_w  = (const float*)d_in[5];
    const float* w2d45  = (const float*)d_in[6];
    const float* b2d45  = (const float*)d_in[7];
    const float* seg_w  = (const float*)d_in[8];
    const float* seg_b  = (const float*)d_in[9];
    const float* so_w   = (const float*)d_in[10];
    const float* so_b   = (const float*)d_in[11];
    const float* sp_wa  = (const float*)d_in[12];
    const float* sp_ba  = (const float*)d_in[13];
    const float* sp_wb  = (const float*)d_in[14];
    const float* sp_bb  = (const float*)d_in[15];
    const float* sp_sw  = (const float*)d_in[16];
    const float* sp_sb  = (const float*)d_in[17];
    const float* fuse   = (const float*)d_in[18];
    float* out = (float*)d_out;

    float *sa1, *sa2, *sa3, *feat;
    cudaGetSymbolAddress((void**)&sa1,  g_sa1);
    cudaGetSymbolAddress((void**)&sa2,  g_sa2);
    cudaGetSymbolAddress((void**)&sa3,  g_sa3);
    cudaGetSymbolAddress((void**)&feat, g_feat);

    // smem: weights chunk (float) + depth-pair input chunk (float2)
    const int SMEM16 = 4*63*16*4 + 4*13*169*8;   // 16,128 + 70,304 = 86,432 B (2 blocks/SM)
    const int SMEM1  = 1*63*16*4 + 1*13*169*8;   // 21,608 B
    cudaFuncSetAttribute((const void*)conv3d7_kernel<16,4>, cudaFuncAttributeMaxDynamicSharedMemorySize, SMEM16);
    cudaFuncSetAttribute((const void*)conv3d7_kernel<1,1>,  cudaFuncAttributeMaxDynamicSharedMemorySize, SMEM1);

    zero_kernel<<<(out_size + 255)/256, 256>>>(out, out_size);

    conv3d7_kernel<1,1><<<dim3(16, BB), 256, SMEM1>>>(x, w3d1, b3d1, sa1);
    cpr_kernel<<<dim3(16, BB), 128>>>(sa1, cpr_w + 0*2048, feat + 0*(BB*FEAT_SZ));

    conv3d7_kernel<16,4><<<dim3(16, BB), 256, SMEM16>>>(sa1, w3d23, b3d23, sa2);
    cpr_kernel<<<dim3(16, BB), 128>>>(sa2, cpr_w + 1*2048, feat + 1*(BB*FEAT_SZ));

    conv3d7_kernel<16,4><<<dim3(16, BB), 256, SMEM16>>>(sa2, w3d23 + 16128, b3d23 + 16, sa3);
    cpr_kernel<<<dim3(16, BB), 128>>>(sa3, cpr_w + 2*2048, feat + 2*(BB*FEAT_SZ));

    conv45_kernel<<<BB, 128>>>(feat + 2*(BB*FEAT_SZ), w2d45, b2d45,
                               feat + 3*(BB*FEAT_SZ), feat + 4*(BB*FEAT_SZ));

    side_kernel<<<dim3(5, BB), 128>>>(x, feat, seg_w, seg_b, so_w, so_b,
                                      sp_wa, sp_ba, sp_wb, sp_bb, sp_sw, sp_sb,
                                      fuse, out);
}

// round 8
// speedup vs baseline: 1.0406x; 1.0201x over previous
#include <cuda_runtime.h>
#include <cuda_bf16.h>

// Problem constants
#define BB   64
#define DPT  128
#define HW   121     // 11*11
#define OCH  16

typedef unsigned long long u64;

union F2U { u64 u; float2 f; };

__device__ __forceinline__ u64 fma2(u64 a, u64 b, u64 c) {
    u64 d;
    asm("fma.rn.f32x2 %0, %1, %2, %3;" : "=l"(d) : "l"(a), "l"(b), "l"(c));
    return d;
}
__device__ __forceinline__ u64 dup2(float w) {
    u64 d;
    asm("mov.b64 %0, {%1, %1};" : "=l"(d) : "f"(w));
    return d;
}

// Scratch (device globals: allocation-free)
__device__ float g_sa1[BB*OCH*DPT*HW];
__device__ float g_sa2[BB*OCH*DPT*HW];
__device__ float g_feat[5*BB*OCH*HW];   // 5 feats of (B,16,11,11)
__device__ float g_alpha[3*OCH*DPT];    // softmax(cpr_w) per layer

#define FEAT_SZ (OCH*HW)         // 1936

// ---------------------------------------------------------------------------
// alpha = softmax over d of cpr_w[l][o][:]; grid 48 blocks (l*16+o), 128 thr
// ---------------------------------------------------------------------------
__global__ void alpha_kernel(const float* __restrict__ cw, float* __restrict__ alpha)
{
    const int lo = blockIdx.x, tid = threadIdx.x;
    __shared__ float red[128];
    float wv = cw[lo*128 + tid];
    red[tid] = wv; __syncthreads();
    for (int s = 64; s > 0; s >>= 1) { if (tid < s) red[tid] = fmaxf(red[tid], red[tid+s]); __syncthreads(); }
    float mx = red[0]; __syncthreads();
    float e = expf(wv - mx);
    red[tid] = e; __syncthreads();
    for (int s = 64; s > 0; s >>= 1) { if (tid < s) red[tid] += red[tid+s]; __syncthreads(); }
    alpha[lo*128 + tid] = e / red[0];
}

// ---------------------------------------------------------------------------
// 3D conv, packed f32x2 FMAs over DEPTH PAIRS, khw-outer register-cached depth
// column, kd+1 weight PREFETCH, fused cpr partial-reduction epilogue.
//
// Per khw: 13 LDS.64 input + 14 LDS.128 weights (prefetched one kd ahead so
// FFMA2 streams never wait on LDS latency) + 224 FFMA2/thread.
// Epilogue: relu(+bias), optional sa store, and atomicAdd of
// sum_d alpha[o][d]*relu(v) into feat[b,o,pos] (cpr fused; outer relu later).
// ---------------------------------------------------------------------------
template<int ICH, int CHK, bool WRITE_SA>
__global__ void __launch_bounds__(256, 2) conv3d8_kernel(
    const float* __restrict__ in, const float* __restrict__ wt,
    const float* __restrict__ bias, float* __restrict__ out,
    const float* __restrict__ alpha, float* __restrict__ featL)
{
    const int d0 = blockIdx.x * 8;
    const int b  = blockIdx.y;
    extern __shared__ float sm[];
    float*  w_s = sm;                               // CHK*63*16 floats
    float2* in2 = (float2*)(sm + CHK*63*16);        // CHK*13*169 float2 (depth pairs)
    __shared__ float alpha_s[16*8];
    const int tid = threadIdx.x;

    // stage this block's alpha window alpha[o][d0..d0+7]
    if (tid < 128) alpha_s[tid] = alpha[(tid >> 3)*128 + d0 + (tid & 7)];

    const int og  = tid >> 7;
    const int pos = tid & 127;
    const int cpos = pos < HW ? pos : HW-1;       // clamp dead lanes (no smem OOB)
    const int h = cpos / 11, w = cpos - h*11;
    const int ppc = (h+1)*13 + (w+1);

    u64 acc[4][8];   // [depth-pair][out-channel]
    #pragma unroll
    for (int r = 0; r < 4; r++)
        #pragma unroll
        for (int o = 0; o < 8; o++) acc[r][o] = 0ULL;

    for (int c0 = 0; c0 < ICH; c0 += CHK) {
        __syncthreads();
        // stage weights: src wt[o][(c0+ii)*63 + r] -> w_s[(ii*63+r)*16 + o]
        for (int t = tid; t < OCH*CHK*63; t += 256) {
            int o = t / (CHK*63);
            int r = t - o*(CHK*63);
            w_s[r*16 + o] = wt[o*(ICH*63) + c0*63 + r];
        }
        // stage input depth-pairs: rows dd=0..12, (in[gd], in[gd+1]), gd=d0-3+dd
        for (int t = tid; t < CHK*13*169; t += 256) {
            int ii  = t / (13*169);
            int rem = t - ii*(13*169);
            int dd  = rem / 169;
            int pp  = rem - dd*169;
            int h13 = pp / 13, w13 = pp - h13*13;
            int gd  = d0 - 3 + dd;
            float v0 = 0.f, v1 = 0.f;
            if (h13 >= 1 && h13 <= 11 && w13 >= 1 && w13 <= 11) {
                const float* src = in + ((size_t)(b*ICH + c0 + ii)*DPT)*HW + (h13-1)*11 + (w13-1);
                if (gd   >= 0 && gd   < DPT) v0 = src[(size_t)gd*HW];
                if (gd+1 >= 0 && gd+1 < DPT) v1 = src[(size_t)(gd+1)*HW];
            }
            in2[t] = make_float2(v0, v1);
        }
        __syncthreads();

        for (int ii = 0; ii < CHK; ++ii) {
            const u64*   col = (const u64*)in2 + (ii*13)*169 + ppc;
            const float* wb  = w_s + ii*63*16 + og*8;
            #pragma unroll 1
            for (int khw = 0; khw < 9; ++khw) {
                const int kh = khw / 3, kw = khw - kh*3;
                const int off = (kh - 1)*13 + (kw - 1);
                // register-cache the 13 depth rows at this spatial tap
                u64 t[13];
                #pragma unroll
                for (int j = 0; j < 13; ++j) t[j] = col[j*169 + off];
                // prefetch kd=0 weights
                float4 wa = *reinterpret_cast<const float4*>(wb + khw*16);
                float4 wc = *reinterpret_cast<const float4*>(wb + khw*16 + 4);
                #pragma unroll
                for (int kd = 0; kd < 7; ++kd) {
                    float4 cwa = wa, cwc = wc;
                    if (kd < 6) {   // prefetch kd+1 weights before this kd's FMAs
                        const float* wn = wb + ((kd+1)*9 + khw)*16;
                        wa = *reinterpret_cast<const float4*>(wn);
                        wc = *reinterpret_cast<const float4*>(wn + 4);
                    }
                    u64 wd[8];
                    wd[0] = dup2(cwa.x); wd[1] = dup2(cwa.y);
                    wd[2] = dup2(cwa.z); wd[3] = dup2(cwa.w);
                    wd[4] = dup2(cwc.x); wd[5] = dup2(cwc.y);
                    wd[6] = dup2(cwc.z); wd[7] = dup2(cwc.w);
                    #pragma unroll
                    for (int r = 0; r < 4; ++r) {
                        u64 a = t[kd + 2*r];
                        #pragma unroll
                        for (int o = 0; o < 8; ++o)
                            acc[r][o] = fma2(a, wd[o], acc[r][o]);
                    }
                }
            }
        }
    }
    __syncthreads();   // alpha_s visible (also covers last chunk)

    if (pos < HW) {
        #pragma unroll
        for (int o = 0; o < 8; ++o) {
            const int oc = og*8 + o;
            const float bv = bias[oc];
            float* ob = out + ((size_t)(b*OCH + oc)*DPT + d0)*HW + pos;
            float fs = 0.f;
            #pragma unroll
            for (int r = 0; r < 4; ++r) {
                F2U a; a.u = acc[r][o];
                float v0 = fmaxf(a.f.x + bv, 0.f);
                float v1 = fmaxf(a.f.y + bv, 0.f);
                if (WRITE_SA) {
                    ob[(2*r  )*HW] = v0;
                    ob[(2*r+1)*HW] = v1;
                }
                fs += alpha_s[oc*8 + 2*r]*v0 + alpha_s[oc*8 + 2*r + 1]*v1;
            }
            atomicAdd(&featL[b*FEAT_SZ + oc*HW + pos], fs);
        }
    }
}

// ---------------------------------------------------------------------------
// relu in place (outer relu of cpr)
// ---------------------------------------------------------------------------
__global__ void relu_kernel(float* x, int n)
{
    int t = blockIdx.x*blockDim.x + threadIdx.x;
    if (t < n) x[t] = fmaxf(x[t], 0.f);
}

// ---------------------------------------------------------------------------
// conv4/conv5 2D: relu(conv2d(3x3,pad1)) twice. One block per batch.
// ---------------------------------------------------------------------------
__global__ void conv45_kernel(const float* __restrict__ feat2,
                              const float* __restrict__ w45, const float* __restrict__ b45,
                              float* __restrict__ feat3, float* __restrict__ feat4)
{
    const int b = blockIdx.x, tid = threadIdx.x;
    __shared__ float fa[FEAT_SZ], fb[FEAT_SZ];
    for (int t = tid; t < FEAT_SZ; t += 128) fa[t] = feat2[b*FEAT_SZ + t];
    __syncthreads();
    if (tid < HW) {
        int h = tid / 11, w = tid - h*11;
        for (int o = 0; o < 16; o++) {
            float acc = b45[o];
            for (int c = 0; c < 16; c++)
                #pragma unroll
                for (int kh = 0; kh < 3; kh++) {
                    int hh = h + kh - 1; if (hh < 0 || hh >= 11) continue;
                    #pragma unroll
                    for (int kw = 0; kw < 3; kw++) {
                        int ww2 = w + kw - 1; if (ww2 < 0 || ww2 >= 11) continue;
                        acc += fa[c*HW + hh*11 + ww2] * w45[(o*16 + c)*9 + kh*3 + kw];
                    }
                }
            float v = acc > 0.f ? acc : 0.f;
            fb[o*HW + tid] = v;
            feat3[b*FEAT_SZ + o*HW + tid] = v;
        }
    }
    __syncthreads();
    if (tid < HW) {
        int h = tid / 11, w = tid - h*11;
        for (int o = 0; o < 16; o++) {
            float acc = b45[16 + o];
            for (int c = 0; c < 16; c++)
                #pragma unroll
                for (int kh = 0; kh < 3; kh++) {
                    int hh = h + kh - 1; if (hh < 0 || hh >= 11) continue;
                    #pragma unroll
                    for (int kw = 0; kw < 3; kw++) {
                        int ww2 = w + kw - 1; if (ww2 < 0 || ww2 >= 11) continue;
                        acc += fb[c*HW + hh*11 + ww2] * w45[2304 + (o*16 + c)*9 + kh*3 + kw];
                    }
                }
            float v = acc > 0.f ? acc : 0.f;
            feat4[b*FEAT_SZ + o*HW + tid] = v;
        }
    }
}

// ---------------------------------------------------------------------------
// Side head: per (side i, batch b). Sideout, seg conv, top-5 similar sum,
// receptive-field-reduced sp branch (only 7x7 ratio patch matters), fuse.
// ---------------------------------------------------------------------------
__global__ void side_kernel(const float* __restrict__ x, const float* __restrict__ feat,
    const float* __restrict__ sw,  const float* __restrict__ sb,
    const float* __restrict__ sow, const float* __restrict__ sob,
    const float* __restrict__ wa,  const float* __restrict__ ba,
    const float* __restrict__ wb,  const float* __restrict__ bbv,
    const float* __restrict__ ssw, const float* __restrict__ ssb,
    const float* __restrict__ fuse, float* __restrict__ out)
{
    const int i = blockIdx.x, b = blockIdx.y, tid = threadIdx.x;
    __shared__ float f_s[FEAT_SZ], act_s[HW], diff_s[HW], s_arr[128], xc[128], y1_s[144], y2_s[16];
    __shared__ int idx_s[5];

    for (int t = tid; t < FEAT_SZ; t += 128)
        f_s[t] = feat[i*(BB*FEAT_SZ) + b*FEAT_SZ + t];
    __syncthreads();

    // seg conv (no relu)
    if (tid < HW) {
        int h = tid / 11, w = tid - h*11;
        float acc = sb[i];
        for (int c = 0; c < 16; c++)
            #pragma unroll
            for (int kh = 0; kh < 3; kh++) {
                int hh = h + kh - 1; if (hh < 0 || hh >= 11) continue;
                #pragma unroll
                for (int kw = 0; kw < 3; kw++) {
                    int ww2 = w + kw - 1; if (ww2 < 0 || ww2 >= 11) continue;
                    acc += f_s[c*HW + hh*11 + ww2] * sw[(i*16 + c)*9 + kh*3 + kw];
                }
            }
        act_s[tid] = acc;
    }
    __syncthreads();
    if (tid < HW) diff_s[tid] = fabsf(act_s[tid] - act_s[60]);
    __syncthreads();
    // top-5 smallest diff, stable (lowest index on ties) — matches jax top_k(-diff)
    if (tid == 0) {
        for (int j = 0; j < 5; j++) {
            float best = 3.4e38f; int bi = 0;
            for (int p = 0; p < HW; p++) { float d = diff_s[p]; if (d < best) { best = d; bi = p; } }
            idx_s[j] = bi; diff_s[bi] = 3.4e38f;
        }
    }
    __syncthreads();
    // similar-sum s[c] and center xc[c]
    {
        float s = 0.f;
        const float* xb = x + (size_t)(b*128 + tid)*HW;
        #pragma unroll
        for (int j = 0; j < 5; j++) s += xb[idx_s[j]];
        s_arr[tid] = s;
        xc[tid] = xb[60];
    }
    __syncthreads();
    // y1 at the 9 positions {62,64,66}^2 feeding the dil-2 conv center
    for (int t = tid; t < 144; t += 128) {
        int o = t / 9, j = t - o*9;
        int pj = 62 + 2*(j/3), qj = 62 + 2*(j%3);
        float acc = ba[i*16 + o];
        #pragma unroll
        for (int ch = 0; ch < 2; ch++) {
            const float* num = ch ? xc : s_arr;
            #pragma unroll
            for (int eh = 0; eh < 3; eh++)
                #pragma unroll
                for (int ew = 0; ew < 3; ew++) {
                    int r = pj + eh - 1, c = qj + ew - 1;
                    float den = num[c];
                    den = fabsf(den) < 0.01f ? 0.01f : den;
                    float img = num[r] / den;
                    acc += img * wa[(((i*16 + o)*2 + ch)*3 + eh)*3 + ew];
                }
        }
        y1_s[o*9 + j] = acc > 0.f ? acc : 0.f;
    }
    __syncthreads();
    // y2 center (dil-2 conv), relu
    if (tid < 16) {
        float acc = bbv[i*16 + tid];
        for (int c = 0; c < 16; c++)
            #pragma unroll
            for (int j = 0; j < 9; j++)
                acc += y1_s[c*9 + j] * wb[((i*16 + tid)*16 + c)*9 + j];
        y2_s[tid] = acc > 0.f ? acc : 0.f;
    }
    __syncthreads();
    // sideouts + fuse
    if (tid < 16) {
        float sa_v = sob[i*16 + tid];
        for (int k = 0; k < 16; k++) sa_v += f_s[k*HW + 60] * sow[(i*16 + tid)*16 + k];
        float sp_v = ssb[i*16 + tid];
        for (int c = 0; c < 16; c++) sp_v += y2_s[c] * ssw[(i*16 + tid)*16 + c];
        atomicAdd(&out[b*16 + tid], fuse[i]*sa_v + fuse[5 + i]*sp_v);
    }
}

__global__ void zero_kernel(float* out, int n)
{
    int t = blockIdx.x*blockDim.x + threadIdx.x;
    if (t < n) out[t] = 0.f;
}

// ---------------------------------------------------------------------------
extern "C" void kernel_launch(void* const* d_in, const int* in_sizes, int n_in,
                              void* d_out, int out_size)
{
    const float* x      = (const float*)d_in[0];
    const float* w3d1   = (const float*)d_in[1];
    const float* b3d1   = (const float*)d_in[2];
    const float* w3d23  = (const float*)d_in[3];
    const float* b3d23  = (const float*)d_in[4];
    const float* cpr_w  = (const float*)d_in[5];
    const float* w2d45  = (const float*)d_in[6];
    const float* b2d45  = (const float*)d_in[7];
    const float* seg_w  = (const float*)d_in[8];
    const float* seg_b  = (const float*)d_in[9];
    const float* so_w   = (const float*)d_in[10];
    const float* so_b   = (const float*)d_in[11];
    const float* sp_wa  = (const float*)d_in[12];
    const float* sp_ba  = (const float*)d_in[13];
    const float* sp_wb  = (const float*)d_in[14];
    const float* sp_bb  = (const float*)d_in[15];
    const float* sp_sw  = (const float*)d_in[16];
    const float* sp_sb  = (const float*)d_in[17];
    const float* fuse   = (const float*)d_in[18];
    float* out = (float*)d_out;

    float *sa1, *sa2, *feat, *alpha;
    cudaGetSymbolAddress((void**)&sa1,   g_sa1);
    cudaGetSymbolAddress((void**)&sa2,   g_sa2);
    cudaGetSymbolAddress((void**)&feat,  g_feat);
    cudaGetSymbolAddress((void**)&alpha, g_alpha);

    // smem: weights chunk (float) + depth-pair input chunk (float2)
    const int SMEM16 = 4*63*16*4 + 4*13*169*8;   // 86,432 B (2 blocks/SM)
    const int SMEM1  = 1*63*16*4 + 1*13*169*8;   // 21,608 B
    cudaFuncSetAttribute((const void*)conv3d8_kernel<16,4,true>,  cudaFuncAttributeMaxDynamicSharedMemorySize, SMEM16);
    cudaFuncSetAttribute((const void*)conv3d8_kernel<16,4,false>, cudaFuncAttributeMaxDynamicSharedMemorySize, SMEM16);
    cudaFuncSetAttribute((const void*)conv3d8_kernel<1,1,true>,   cudaFuncAttributeMaxDynamicSharedMemorySize, SMEM1);

    alpha_kernel<<<48, 128>>>(cpr_w, alpha);
    zero_kernel<<<(out_size + 255)/256, 256>>>(out, out_size);
    zero_kernel<<<(3*BB*FEAT_SZ + 255)/256, 256>>>(feat, 3*BB*FEAT_SZ);

    conv3d8_kernel<1,1,true><<<dim3(16, BB), 256, SMEM1>>>(
        x, w3d1, b3d1, sa1, alpha + 0*2048, feat + 0*(BB*FEAT_SZ));

    conv3d8_kernel<16,4,true><<<dim3(16, BB), 256, SMEM16>>>(
        sa1, w3d23, b3d23, sa2, alpha + 1*2048, feat + 1*(BB*FEAT_SZ));

    conv3d8_kernel<16,4,false><<<dim3(16, BB), 256, SMEM16>>>(
        sa2, w3d23 + 16128, b3d23 + 16, sa1 /*unused*/, alpha + 2*2048, feat + 2*(BB*FEAT_SZ));

    relu_kernel<<<(3*BB*FEAT_SZ + 255)/256, 256>>>(feat, 3*BB*FEAT_SZ);

    conv45_kernel<<<BB, 128>>>(feat + 2*(BB*FEAT_SZ), w2d45, b2d45,
                               feat + 3*(BB*FEAT_SZ), feat + 4*(BB*FEAT_SZ));

    side_kernel<<<dim3(5, BB), 128>>>(x, feat, seg_w, seg_b, so_w, so_b,
                                      sp_wa, sp_ba, sp_wb, sp_bb, sp_sw, sp_sb,
                                      fuse, out);
}